// round 1
// baseline (speedup 1.0000x reference)
#include <cuda_runtime.h>
#include <cstdint>

#define B_ROWS   65536
#define OUT_N    2048
#define IN_K     64
#define BM       128
#define BN       128
#define TM       8
#define TN       8
#define NTHREADS 256

typedef unsigned long long ull;

// Duplicate a float into both lanes of an f32x2 register pair.
__device__ __forceinline__ ull dup_f32(float x) {
    ull r;
    asm("mov.b64 %0, {%1, %1};" : "=l"(r) : "f"(x));
    return r;
}

// d = a * b + d on packed f32x2 (Blackwell FFMA2 path, 2x fp32 FMA throughput).
__device__ __forceinline__ void ffma2(ull& d, ull a, ull b) {
    asm("fma.rn.f32x2 %0, %1, %2, %0;" : "+l"(d) : "l"(a), "l"(b));
}

__device__ __forceinline__ void unpack2(ull v, float& lo, float& hi) {
    asm("mov.b64 {%0, %1}, %2;" : "=f"(lo), "=f"(hi) : "l"(v));
}

extern __shared__ float smem[];

__global__ __launch_bounds__(NTHREADS, 2)
void rbf_gaussian_kernel(const float* __restrict__ input,
                         const float* __restrict__ centers,
                         const float* __restrict__ log_sigmas,
                         float* __restrict__ out) {
    // Dynamic smem layout (all fp32):
    //   As[IN_K][BM]  k-major x tile        (32 KB)
    //   Bs[IN_K][BN]  k-major centers tile  (32 KB)
    //   x2s[BM], c2s[BN], is2[BN]           (1.5 KB)
    float* As  = smem;
    float* Bs  = As + IN_K * BM;
    float* x2s = Bs + IN_K * BN;
    float* c2s = x2s + BM;
    float* is2 = c2s + BN;

    const int tid  = threadIdx.x;
    const int row0 = blockIdx.y * BM;
    const int col0 = blockIdx.x * BN;

    // ---- Load tiles (row-major gmem -> k-major smem) ----
    {
        const float* Ag = input + (size_t)row0 * IN_K;
        #pragma unroll
        for (int i = 0; i < (BM * IN_K / 4) / NTHREADS; i++) {
            int idx = tid + i * NTHREADS;          // 0..2047
            int r = idx >> 4;
            int k = (idx & 15) << 2;
            float4 v = *(const float4*)(Ag + r * IN_K + k);
            As[(k + 0) * BM + r] = v.x;
            As[(k + 1) * BM + r] = v.y;
            As[(k + 2) * BM + r] = v.z;
            As[(k + 3) * BM + r] = v.w;
        }
        const float* Bg = centers + (size_t)col0 * IN_K;
        #pragma unroll
        for (int i = 0; i < (BN * IN_K / 4) / NTHREADS; i++) {
            int idx = tid + i * NTHREADS;
            int c = idx >> 4;
            int k = (idx & 15) << 2;
            float4 v = *(const float4*)(Bg + c * IN_K + k);
            Bs[(k + 0) * BN + c] = v.x;
            Bs[(k + 1) * BN + c] = v.y;
            Bs[(k + 2) * BN + c] = v.z;
            Bs[(k + 3) * BN + c] = v.w;
        }
    }
    __syncthreads();

    // ---- Per-row / per-col auxiliaries (||x||^2, ||c||^2, 1/sigma^2) ----
    if (tid < BM) {
        float s = 0.f;
        #pragma unroll
        for (int k = 0; k < IN_K; k++) {
            float v = As[k * BM + tid];
            s = fmaf(v, v, s);
        }
        x2s[tid] = s;
    } else {
        int c = tid - BM;  // 0..127 (BN == 128, NTHREADS == 256)
        float s = 0.f;
        #pragma unroll
        for (int k = 0; k < IN_K; k++) {
            float v = Bs[k * BN + c];
            s = fmaf(v, v, s);
        }
        c2s[c] = s;
        is2[c] = __expf(-2.f * log_sigmas[col0 + c]);
    }

    // ---- Main GEMM: dot = x . c via packed f32x2 FMA ----
    const int tx = tid & 15;
    const int ty = tid >> 4;
    const int rb = ty * TM;   // local row base
    const int cb = tx * TN;   // local col base

    ull acc[TM][TN / 2];
    #pragma unroll
    for (int r = 0; r < TM; r++)
        #pragma unroll
        for (int j = 0; j < TN / 2; j++)
            acc[r][j] = 0ull;  // bit pattern {0.f, 0.f}

    #pragma unroll 16
    for (int k = 0; k < IN_K; k++) {
        const float4 a0 = *(const float4*)(As + k * BM + rb);
        const float4 a1 = *(const float4*)(As + k * BM + rb + 4);
        const ulonglong2 b01 = *(const ulonglong2*)(Bs + k * BN + cb);
        const ulonglong2 b23 = *(const ulonglong2*)(Bs + k * BN + cb + 4);

        ull ap[TM];
        ap[0] = dup_f32(a0.x); ap[1] = dup_f32(a0.y);
        ap[2] = dup_f32(a0.z); ap[3] = dup_f32(a0.w);
        ap[4] = dup_f32(a1.x); ap[5] = dup_f32(a1.y);
        ap[6] = dup_f32(a1.z); ap[7] = dup_f32(a1.w);

        ull bv[4];
        bv[0] = b01.x; bv[1] = b01.y; bv[2] = b23.x; bv[3] = b23.y;

        #pragma unroll
        for (int r = 0; r < TM; r++)
            #pragma unroll
            for (int j = 0; j < TN / 2; j++)
                ffma2(acc[r][j], ap[r], bv[j]);
    }

    __syncthreads();  // x2s/c2s/is2 visible to all

    // ---- Epilogue: sq = max(x2 - 2*dot + c2, 0); out = exp(-sq/sigma^2) ----
    #pragma unroll
    for (int r = 0; r < TM; r++) {
        const float x2r = x2s[rb + r];
        float res[TN];
        #pragma unroll
        for (int j = 0; j < TN / 2; j++) {
            float lo, hi;
            unpack2(acc[r][j], lo, hi);
            const int c = cb + 2 * j;
            float t0 = x2r + c2s[c];
            float t1 = x2r + c2s[c + 1];
            float sq0 = fmaxf(fmaf(-2.f, lo, t0), 0.f);
            float sq1 = fmaxf(fmaf(-2.f, hi, t1), 0.f);
            res[2 * j]     = __expf(-sq0 * is2[c]);
            res[2 * j + 1] = __expf(-sq1 * is2[c + 1]);
        }
        float4* op = (float4*)(out + (size_t)(row0 + rb + r) * OUT_N + col0 + cb);
        op[0] = make_float4(res[0], res[1], res[2], res[3]);
        op[1] = make_float4(res[4], res[5], res[6], res[7]);
    }
}

extern "C" void kernel_launch(void* const* d_in, const int* in_sizes, int n_in,
                              void* d_out, int out_size) {
    (void)in_sizes; (void)n_in; (void)out_size;
    const float* input      = (const float*)d_in[0];
    const float* centers    = (const float*)d_in[1];
    const float* log_sigmas = (const float*)d_in[2];
    float* out              = (float*)d_out;

    const int smem_bytes = (IN_K * BM + IN_K * BN + BM + 2 * BN) * (int)sizeof(float);
    cudaFuncSetAttribute(rbf_gaussian_kernel,
                         cudaFuncAttributeMaxDynamicSharedMemorySize, smem_bytes);

    dim3 grid(OUT_N / BN, B_ROWS / BM);  // (16, 512)
    rbf_gaussian_kernel<<<grid, NTHREADS, smem_bytes>>>(input, centers, log_sigmas, out);
}

// round 3
// speedup vs baseline: 3.1267x; 3.1267x over previous
#include <cuda_runtime.h>
#include <cuda_bf16.h>
#include <cstdint>

#define B_ROWS   65536
#define OUT_N    2048
#define IN_K     64
#define BM       128
#define BN       128
#define NTHREADS 256

// ---------------- scratch (__device__ globals: allocation-free) ----------------
// X' chunks: [Xh, Xh, Xl]; C' chunks: [Ch, Cl, Ch]  -> ChXh + ClXh + ChXl
__device__ __nv_bfloat16 g_X[3ull * B_ROWS * IN_K];
__device__ __nv_bfloat16 g_C[3ull * OUT_N * IN_K];
__device__ float g_x2[B_ROWS];
__device__ float g_c2[OUT_N];
__device__ float g_e2[OUT_N];      // -exp(-2*log_sigma) * log2(e)

// ---------------- PTX helpers (all sm_80-era, no 'a' features) ----------------
__device__ __forceinline__ uint32_t smem_u32(const void* p) {
    uint32_t a;
    asm("{ .reg .u64 t; cvta.to.shared.u64 t, %1; cvt.u32.u64 %0, t; }" : "=r"(a) : "l"(p));
    return a;
}
__device__ __forceinline__ void cp16(uint32_t s, const void* g) {
    asm volatile("{ .reg .u64 ga; cvta.to.global.u64 ga, %1; cp.async.cg.shared.global [%0], [ga], 16; }"
                 :: "r"(s), "l"(g) : "memory");
}
#define CP_COMMIT() asm volatile("cp.async.commit_group;" ::: "memory")
#define CP_WAIT0()  asm volatile("cp.async.wait_group 0;" ::: "memory")

#define LDSM4(r, a) \
    asm volatile("ldmatrix.sync.aligned.m8n8.x4.shared.b16 {%0,%1,%2,%3}, [%4];" \
        : "=r"((r)[0]), "=r"((r)[1]), "=r"((r)[2]), "=r"((r)[3]) : "r"(a))

#define MMA16816(d, a, b0, b1) \
    asm volatile("mma.sync.aligned.m16n8k16.row.col.f32.bf16.bf16.f32 " \
        "{%0,%1,%2,%3}, {%4,%5,%6,%7}, {%8,%9}, {%0,%1,%2,%3};" \
        : "+f"((d)[0]), "+f"((d)[1]), "+f"((d)[2]), "+f"((d)[3]) \
        : "r"((a)[0]), "r"((a)[1]), "r"((a)[2]), "r"((a)[3]), "r"(b0), "r"(b1))

// ---------------- prep kernels: fp32 -> (hi, lo) bf16 split + norms ----------------
__global__ void prep_input(const float* __restrict__ inp) {
    int g = blockIdx.x * blockDim.x + threadIdx.x;     // B_ROWS*16 threads
    int row = g >> 4, seg = g & 15;
    const float4 v = *(const float4*)(inp + (size_t)row * IN_K + seg * 4);
    float vv[4] = {v.x, v.y, v.z, v.w};
    float s = 0.f;
    __nv_bfloat16 h[4], l[4];
    #pragma unroll
    for (int i = 0; i < 4; i++) {
        s = fmaf(vv[i], vv[i], s);
        h[i] = __float2bfloat16(vv[i]);
        l[i] = __float2bfloat16(vv[i] - __bfloat162float(h[i]));
    }
    uint2 hp, lp;
    memcpy(&hp, h, 8); memcpy(&lp, l, 8);
    size_t base = (size_t)row * IN_K + seg * 4;
    const size_t CH = (size_t)B_ROWS * IN_K;
    *(uint2*)(g_X + base)          = hp;   // chunk 0: hi
    *(uint2*)(g_X + CH + base)     = hp;   // chunk 1: hi
    *(uint2*)(g_X + 2 * CH + base) = lp;   // chunk 2: lo
    #pragma unroll
    for (int m = 1; m <= 8; m <<= 1) s += __shfl_xor_sync(~0u, s, m);
    if (seg == 0) g_x2[row] = s;
}

__global__ void prep_centers(const float* __restrict__ cen, const float* __restrict__ ls) {
    int g = blockIdx.x * blockDim.x + threadIdx.x;     // OUT_N*16 threads
    int row = g >> 4, seg = g & 15;
    const float4 v = *(const float4*)(cen + (size_t)row * IN_K + seg * 4);
    float vv[4] = {v.x, v.y, v.z, v.w};
    float s = 0.f;
    __nv_bfloat16 h[4], l[4];
    #pragma unroll
    for (int i = 0; i < 4; i++) {
        s = fmaf(vv[i], vv[i], s);
        h[i] = __float2bfloat16(vv[i]);
        l[i] = __float2bfloat16(vv[i] - __bfloat162float(h[i]));
    }
    uint2 hp, lp;
    memcpy(&hp, h, 8); memcpy(&lp, l, 8);
    size_t base = (size_t)row * IN_K + seg * 4;
    const size_t CH = (size_t)OUT_N * IN_K;
    *(uint2*)(g_C + base)          = hp;   // chunk 0: hi
    *(uint2*)(g_C + CH + base)     = lp;   // chunk 1: lo
    *(uint2*)(g_C + 2 * CH + base) = hp;   // chunk 2: hi
    #pragma unroll
    for (int m = 1; m <= 8; m <<= 1) s += __shfl_xor_sync(~0u, s, m);
    if (seg == 0) {
        g_c2[row] = s;
        g_e2[row] = -1.4426950408889634f * expf(-2.f * ls[row]);
    }
}

// ---------------- main: HMMA GEMM + fused gaussian epilogue ----------------
// smem per chunk tile: [128 rows][64 bf16] = 128 B/row, XOR-swizzled in 16B units.
extern __shared__ char smem_raw[];

__global__ __launch_bounds__(NTHREADS, 2)
void rbf_hmma(float* __restrict__ out) {
    __nv_bfloat16* sA = (__nv_bfloat16*)smem_raw;        // 3*128*64 bf16 = 48 KB
    __nv_bfloat16* sB = sA + 3 * BM * IN_K;              // 48 KB
    float* x2s = (float*)(sB + 3 * BN * IN_K);           // 128 f
    float* c2s = x2s + BM;                               // 128 f
    float* e2s = c2s + BN;                               // 128 f

    const int tid  = threadIdx.x;
    const int col0 = blockIdx.x * BN;    // center tile (fast dim -> L2 reuse of x tile)
    const int row0 = blockIdx.y * BM;

    const uint32_t sAu = smem_u32(sA);
    const uint32_t sBu = smem_u32(sB);

    // ---- async tile loads: 3 chunks x [128][64] bf16, swizzled ----
    #pragma unroll
    for (int i = 0; i < 12; i++) {
        int u = tid + i * NTHREADS;          // 0..3071
        int ch = u >> 10, rem = u & 1023;
        int r = rem >> 3, c = rem & 7;
        uint32_t so = ch * 16384 + r * 128 + ((c ^ (r & 7)) << 4);
        cp16(sAu + so, g_X + (size_t)ch * (B_ROWS * IN_K) + (size_t)(row0 + r) * IN_K + c * 8);
        cp16(sBu + so, g_C + (size_t)ch * (OUT_N * IN_K) + (size_t)(col0 + r) * IN_K + c * 8);
    }
    CP_COMMIT();

    if (tid < BM) {
        x2s[tid] = g_x2[row0 + tid];
    } else {
        int c = tid - BM;
        c2s[c] = g_c2[col0 + c];
        e2s[c] = g_e2[col0 + c];
    }
    CP_WAIT0();
    __syncthreads();

    // ---- warp tiling: 8 warps = 4 (M) x 2 (N); warp tile 32x64 ----
    const int l   = tid & 31;
    const int wid = tid >> 5;
    const int wr  = wid & 3;       // m: wr*32
    const int wc  = wid >> 2;      // n: wc*64

    // ldmatrix lane base addresses (within one chunk), XOR'd by k-step later
    uint32_t abase[2];
    {
        int hb = l >> 4;                       // k-half select
        #pragma unroll
        for (int mi = 0; mi < 2; mi++) {
            int row = wr * 32 + mi * 16 + (l & 15);
            abase[mi] = row * 128 + ((hb ^ (row & 7)) << 4);
        }
    }
    uint32_t bbase[4];
    {
        int m = l >> 3;                        // matrix index within x4
        int hb = m & 1;
        #pragma unroll
        for (int q = 0; q < 4; q++) {
            int n = wc * 64 + (2 * q + (m >> 1)) * 8 + (l & 7);
            bbase[q] = n * 128 + ((hb ^ (n & 7)) << 4);
        }
    }

    float acc[2][8][4];
    #pragma unroll
    for (int mi = 0; mi < 2; mi++)
        #pragma unroll
        for (int j = 0; j < 8; j++)
            #pragma unroll
            for (int q = 0; q < 4; q++) acc[mi][j][q] = 0.f;

    #pragma unroll
    for (int ks = 0; ks < 12; ks++) {
        const uint32_t co = (ks >> 2) * 16384;       // chunk offset
        const uint32_t kx = (uint32_t)(ks & 3) << 5; // XOR in swizzled 16B-unit space

        uint32_t a[2][4], b[4][4];
        LDSM4(a[0], sAu + co + (abase[0] ^ kx));
        LDSM4(a[1], sAu + co + (abase[1] ^ kx));
        LDSM4(b[0], sBu + co + (bbase[0] ^ kx));
        LDSM4(b[1], sBu + co + (bbase[1] ^ kx));
        LDSM4(b[2], sBu + co + (bbase[2] ^ kx));
        LDSM4(b[3], sBu + co + (bbase[3] ^ kx));

        #pragma unroll
        for (int j = 0; j < 8; j++) {
            uint32_t b0 = b[j >> 1][(j & 1) * 2];
            uint32_t b1 = b[j >> 1][(j & 1) * 2 + 1];
            MMA16816(acc[0][j], a[0], b0, b1);
            MMA16816(acc[1][j], a[1], b0, b1);
        }
    }

    // ---- epilogue: out = exp2((x2 - 2*dot + c2) * e2), e2 = -log2e/sigma^2 ----
    #pragma unroll
    for (int mi = 0; mi < 2; mi++) {
        const int rl = wr * 32 + mi * 16 + (l >> 2);
        const float x2a = x2s[rl];
        const float x2b = x2s[rl + 8];
        float* o0 = out + (size_t)(row0 + rl) * OUT_N + col0;
        float* o1 = o0 + 8 * OUT_N;
        #pragma unroll
        for (int j = 0; j < 8; j++) {
            const int c = wc * 64 + j * 8 + 2 * (l & 3);
            const float c20 = c2s[c],  c21 = c2s[c + 1];
            const float e0  = e2s[c],  e1  = e2s[c + 1];
            const float* A  = acc[mi][j];
            float s0 = fmaxf(fmaf(-2.f, A[0], x2a + c20), 0.f);
            float s1 = fmaxf(fmaf(-2.f, A[1], x2a + c21), 0.f);
            float s2 = fmaxf(fmaf(-2.f, A[2], x2b + c20), 0.f);
            float s3 = fmaxf(fmaf(-2.f, A[3], x2b + c21), 0.f);
            float2 v0 = make_float2(exp2f(s0 * e0), exp2f(s1 * e1));
            float2 v1 = make_float2(exp2f(s2 * e0), exp2f(s3 * e1));
            *(float2*)(o0 + c) = v0;
            *(float2*)(o1 + c) = v1;
        }
    }
}

extern "C" void kernel_launch(void* const* d_in, const int* in_sizes, int n_in,
                              void* d_out, int out_size) {
    (void)in_sizes; (void)n_in; (void)out_size;
    const float* input      = (const float*)d_in[0];
    const float* centers    = (const float*)d_in[1];
    const float* log_sigmas = (const float*)d_in[2];
    float* out              = (float*)d_out;

    const int smem_bytes = 3 * BM * IN_K * 2 + 3 * BN * IN_K * 2
                         + (BM + 2 * BN) * (int)sizeof(float);  // 99840 B
    cudaFuncSetAttribute(rbf_hmma, cudaFuncAttributeMaxDynamicSharedMemorySize, smem_bytes);

    prep_input<<<B_ROWS * 16 / 256, 256>>>(input);
    prep_centers<<<OUT_N * 16 / 256, 256>>>(centers, log_sigmas);
    rbf_hmma<<<dim3(OUT_N / BN, B_ROWS / BM), NTHREADS, smem_bytes>>>(out);
}